// round 17
// baseline (speedup 1.0000x reference)
#include <cuda_runtime.h>
#include <cuda_fp16.h>
#include <cstdint>

#define MAXN 100000

// ---- device scratch (no allocations allowed) ----
// g_deg and g_aggh are SELF-CLEANING: zeroed at module load, and restored to
// zero by k_dinv / k_pool respectively at each run, so no init kernel.
__device__ float g_deg [MAXN];
__device__ float g_dinv[MAXN];
__device__ __align__(128) float4 g_xp  [MAXN];      // xs = dinv*x, padded (w=0)
__device__ __align__(128) float4 g_aggx[MAXN];      // layer-0 agg of xs (fp32)
__device__ __align__(128) float4 g_av  [MAXN];      // (a0,a1,a2,dinv): rank-3 h1 code
__device__ __align__(128) uint2  g_aggh[MAXN * 8];  // layer-1 EDGE agg fp16 [N x 32]

__device__ __forceinline__ void red_add_v4f(float4* addr, float4 v) {
    atomicAdd(addr, v);   // native fp32 vector red (cc >= 9.0)
}
__device__ __forceinline__ void red_add_v4h(void* addr, unsigned int a, unsigned int b,
                                            unsigned int c, unsigned int d) {
    asm volatile("red.global.add.noftz.v4.f16x2 [%0], {%1,%2,%3,%4};"
                 :: "l"(__cvta_generic_to_global(addr)),
                    "r"(a), "r"(b), "r"(c), "r"(d) : "memory");
}

// K2: deg[col] += w, 2 edges per thread (vectorized idx/w loads)
__global__ void k_deg(const int* __restrict__ idx, const float* __restrict__ w, int E) {
    int t = blockIdx.x * blockDim.x + threadIdx.x;
    int e = t * 2;
    if (e + 1 < E) {
        int2   c2 = *(const int2*)(idx + E + e);
        float2 w2 = *(const float2*)(w + e);
        atomicAdd(&g_deg[c2.x], w2.x);
        atomicAdd(&g_deg[c2.y], w2.y);
    } else if (e < E) {
        atomicAdd(&g_deg[idx[E + e]], w[e]);
    }
}

// K3: dinv = rsqrt(1+deg) (self-loop folded); reset deg to 0 for next replay;
// xs = dinv*x; seed layer-0 agg with self term xs.
__global__ void k_dinv(const float* __restrict__ x, int n) {
    int i = blockIdx.x * blockDim.x + threadIdx.x;
    if (i >= n) return;
    float d = g_deg[i];
    g_deg[i] = 0.f;                       // self-clean for graph replay
    float dv = rsqrtf(1.0f + d);
    g_dinv[i] = dv;
    float4 xs = make_float4(x[3*i] * dv, x[3*i+1] * dv, x[3*i+2] * dv, 0.f);
    g_xp[i]   = xs;
    g_aggx[i] = xs;
}

// K4: layer-0 edge pass (factorized norm), fp32 red.v4
__global__ void k_edge0(const int* __restrict__ idx, const float* __restrict__ w, int E) {
    int e = blockIdx.x * blockDim.x + threadIdx.x;
    if (e >= E) return;
    int row = idx[e];
    int col = idx[E + e];
    float ww = w[e];
    float4 v = g_xp[row];
    red_add_v4f(&g_aggx[col], make_float4(v.x * ww, v.y * ww, v.z * ww, 0.f));
}

// K5: tiny av writeout: av = (dinv*agg0, dinv). One thread per node.
// (h1 self-term is recomputed rank-3 in k_pool; edge1 recomputes per edge.)
__global__ void k_node0(int n) {
    int i = blockIdx.x * blockDim.x + threadIdx.x;
    if (i >= n) return;
    float4 ag = g_aggx[i];
    float dv  = g_dinv[i];
    g_av[i] = make_float4(ag.x * dv, ag.y * dv, ag.z * dv, dv);
}

// K6: layer-1 edge pass, rank-3 recompute. Quad of 4 lanes owns a strip of
// NE edges; lane j owns features [8j,8j+8). Per edge: one 16B broadcast av
// gather, 24 FMA recompute, one red.v4.f16x2 into the ZEROED aggh.
#define NE 8
__global__ void k_edge1(const int* __restrict__ idx, const float* __restrict__ w,
                        const float* __restrict__ W0, const float* __restrict__ b0, int E) {
    int t  = blockIdx.x * blockDim.x + threadIdx.x;
    int qd = t >> 2;          // quad id
    int j  = t & 3;           // lane-in-quad
    int e0 = qd * NE;
    if (e0 >= E) return;
    float w0r[8], w1r[8], w2r[8], b0r[8];
#pragma unroll
    for (int k = 0; k < 8; k++) {
        int c = 8 * j + k;
        w0r[k] = W0[c]; w1r[k] = W0[32 + c]; w2r[k] = W0[64 + c]; b0r[k] = b0[c];
    }
    int eend = min(e0 + NE, E);
    for (int e = e0; e < eend; e++) {
        int row = idx[e];
        int col = idx[E + e];
        float ww = w[e];
        float4 av = __ldg(g_av + row);          // 16B, quad-broadcast (1 sector)
        float s = av.w * ww;                    // dinv_row * w_e
        float f[8];
#pragma unroll
        for (int k = 0; k < 8; k++) {
            float h = fmaf(av.x, w0r[k], fmaf(av.y, w1r[k], fmaf(av.z, w2r[k], b0r[k])));
            f[k] = fmaxf(h, 0.f) * s;
        }
        half2 p0 = __floats2half2_rn(f[0], f[1]);
        half2 p1 = __floats2half2_rn(f[2], f[3]);
        half2 p2 = __floats2half2_rn(f[4], f[5]);
        half2 p3 = __floats2half2_rn(f[6], f[7]);
        red_add_v4h(&((uint4*)g_aggh)[col * 4 + j],
                    *(unsigned int*)&p0, *(unsigned int*)&p1,
                    *(unsigned int*)&p2, *(unsigned int*)&p3);
    }
}

// K7: per-graph block. For each node: agg1 = aggh_edges + self (recomputed
// rank-3 in fp32); restore aggh to ZERO for the next replay; then
// h2 = relu(dinv*agg1 @ W1 + b1), mean-pool, head dot with Wr.
__global__ void k_pool(const int* __restrict__ batch,
                       const float* __restrict__ W0, const float* __restrict__ b0,
                       const float* __restrict__ W1, const float* __restrict__ b1,
                       const float* __restrict__ Wr, const float* __restrict__ br,
                       float* __restrict__ out, int n) {
    int g = blockIdx.x;
    __shared__ float sW1[32 * 32];
    __shared__ float sb1[32];
    __shared__ float sWr[32];
    __shared__ int   sse[2];
    __shared__ float stile[8][33];
    __shared__ float spool[8][32];
    int tid = threadIdx.x;  // 256 threads
    int feat = tid & 31, slot = tid >> 5;
    for (int k = tid; k < 1024; k += 256) sW1[k] = W1[k];
    if (tid < 32) { sb1[tid] = b1[tid]; sWr[tid] = Wr[tid]; }
    // per-thread self-term coefficients (feat fixed per thread)
    float w0f = W0[feat], w1f = W0[32 + feat], w2f = W0[64 + feat], b0f = b0[feat];
    if (tid < 2) {
        int key = g + tid;
        int lo = 0, hi = n;
        while (lo < hi) { int mid = (lo + hi) >> 1; if (batch[mid] < key) lo = mid + 1; else hi = mid; }
        sse[tid] = lo;
    }
    __syncthreads();
    int start = sse[0], end = sse[1];
    __half* agg = (__half*)g_aggh;
    float acc = 0.f;
    for (int base = start; base < end; base += 8) {
        int nload = min(8, end - base);
        __syncthreads();
        if (slot < nload) {
            int node = base + slot;
            float4 av = g_av[node];          // warp-uniform broadcast
            float dv = av.w;
            float hs = fmaf(av.x, w0f, fmaf(av.y, w1f, fmaf(av.z, w2f, b0f)));
            hs = fmaxf(hs, 0.f) * dv;        // self h1 (pre-scaled by dinv)
            size_t off = (size_t)node * 32 + feat;
            stile[slot][feat] = dv * (__half2float(agg[off]) + hs);
            agg[off] = __ushort_as_half((unsigned short)0);  // self-clean
        }
        __syncthreads();
        if (slot < nload) {
            float v = sb1[feat];
#pragma unroll
            for (int jj = 0; jj < 32; jj++) v = fmaf(stile[slot][jj], sW1[jj * 32 + feat], v);
            acc += fmaxf(v, 0.f);
        }
    }
    spool[slot][feat] = acc;
    __syncthreads();
    if (tid < 32) {
        float s = 0.f;
#pragma unroll
        for (int k = 0; k < 8; k++) s += spool[k][tid];
        float cnt = (float)(end - start);
        float hg = s / fmaxf(cnt, 1.f);
        float p = hg * sWr[tid];
#pragma unroll
        for (int off = 16; off; off >>= 1) p += __shfl_down_sync(0xffffffffu, p, off);
        if (tid == 0) out[g] = p + br[0];
    }
}

extern "C" void kernel_launch(void* const* d_in, const int* in_sizes, int n_in,
                              void* d_out, int out_size) {
    const float* x     = (const float*)d_in[0];
    const int*   ei    = (const int*)d_in[1];
    const float* ew    = (const float*)d_in[2];
    const int*   batch = (const int*)d_in[3];
    const float* W0    = (const float*)d_in[4];
    const float* b0    = (const float*)d_in[5];
    const float* W1    = (const float*)d_in[6];
    const float* b1    = (const float*)d_in[7];
    const float* Wr    = (const float*)d_in[8];
    const float* br    = (const float*)d_in[9];
    float* out = (float*)d_out;

    int n = in_sizes[0] / 3;
    int E = in_sizes[2];
    int G = out_size;
    const int TB = 256;

    int degThreads = (E + 1) / 2;
    k_deg  <<<(degThreads + TB - 1) / TB, TB>>>(ei, ew, E);
    k_dinv <<<(n + TB - 1) / TB, TB>>>(x, n);
    k_edge0<<<(E + TB - 1) / TB, TB>>>(ei, ew, E);
    k_node0<<<(n + TB - 1) / TB, TB>>>(n);
    long long quads = ((long long)E + NE - 1) / NE;
    long long t1 = quads * 4;
    k_edge1<<<(int)((t1 + TB - 1) / TB), TB>>>(ei, ew, W0, b0, E);
    k_pool <<<G, 256>>>(batch, W0, b0, W1, b1, Wr, br, out, n);
}